// round 5
// baseline (speedup 1.0000x reference)
#include <cuda_runtime.h>
#include <stdint.h>

// ============================================================================
// BinaryLinear (sm_100 base ISA — tcgen05 rejected by this toolchain):
//   out = (mean|x| * mean|w|) * sign(x) @ sign(w)^T + bias
//   x: [4,2048,4096] fp32 -> M=8192, K=4096 ; w: [4096,4096] fp32 -> N=4096
// v5 (= v4 resubmit; container-level infra flake, kernel never reached nvcc):
// int8 +/-1 binarize, IMMA m16n8k32 s8 GEMM (exact s32 accumulation),
// 4-stage cp.async pipeline, 80B-padded conflict-free smem, deterministic
// two-stage scale reduction.
// ============================================================================

#define M_DIM 8192
#define N_DIM 4096
#define K_DIM 4096

#define BM 128
#define BN 128
#define BK 64                        // int8 K elements per pipeline chunk
#define NCHUNK (K_DIM / BK)          // 64
#define DEPTH 4

#define ASTRIDE 80                   // bytes per 64B row, padded (bank-conflict-free)
#define A_SM_BYTES (BM * ASTRIDE)    // 10240
#define B_SM_BYTES (BN * ASTRIDE)    // 10240
#define STAGE_BYTES (A_SM_BYTES + B_SM_BYTES)   // 20480
#define SMEM_TOTAL (DEPTH * STAGE_BYTES)        // 81920

// ---- device scratch ----
__device__ int8_t g_Xb[(size_t)M_DIM * K_DIM];   // 32 MB
__device__ int8_t g_Wb[(size_t)N_DIM * K_DIM];   // 16 MB
__device__ float g_partX[2048];
__device__ float g_partW[1024];
__device__ float g_scale;

// ---- helpers ----
__device__ __forceinline__ uint32_t smem_u32(const void* p) {
    uint32_t a;
    asm("{ .reg .u64 t; cvta.to.shared.u64 t, %1; cvt.u32.u64 %0, t; }"
        : "=r"(a) : "l"(p));
    return a;
}

__device__ __forceinline__ void cp16(uint32_t saddr, const void* gaddr) {
    asm volatile("cp.async.cg.shared.global [%0], [%1], 16;\n"
                 :: "r"(saddr), "l"(gaddr));
}
__device__ __forceinline__ void cp_commit() {
    asm volatile("cp.async.commit_group;\n" ::);
}
template <int N>
__device__ __forceinline__ void cp_wait() {
    asm volatile("cp.async.wait_group %0;\n" :: "n"(N));
}

__device__ __forceinline__ uint32_t lds32(uint32_t addr) {
    uint32_t v;
    asm volatile("ld.shared.b32 %0, [%1];" : "=r"(v) : "r"(addr));
    return v;
}

// s8 x s8 -> s32 : D(16x8) += A(16x32) * B(32x8)
__device__ __forceinline__ void imma16832(int* c, const uint32_t* a, const uint32_t* b) {
    asm volatile(
        "mma.sync.aligned.m16n8k32.row.col.s32.s8.s8.s32 "
        "{%0,%1,%2,%3}, {%4,%5,%6,%7}, {%8,%9}, {%0,%1,%2,%3};"
        : "+r"(c[0]), "+r"(c[1]), "+r"(c[2]), "+r"(c[3])
        : "r"(a[0]), "r"(a[1]), "r"(a[2]), "r"(a[3]),
          "r"(b[0]), "r"(b[1]));
}

// ============================================================================
// Phase 1: binarize fp32 -> int8 {-1,+1}, deterministic |.| partial sums
// ============================================================================
__device__ __forceinline__ void prep_body(const float4* __restrict__ in,
                                          uint32_t* __restrict__ out,
                                          int n4, float* __restrict__ partial) {
    float s = 0.f;
    const int stride = gridDim.x * blockDim.x;
    for (int i = blockIdx.x * blockDim.x + threadIdx.x; i < n4; i += stride) {
        float4 v = in[i];
        s += fabsf(v.x) + fabsf(v.y) + fabsf(v.z) + fabsf(v.w);
        uint32_t p = (v.x >= 0.f ? 0x01u : 0xFFu)
                   | ((v.y >= 0.f ? 0x01u : 0xFFu) << 8)
                   | ((v.z >= 0.f ? 0x01u : 0xFFu) << 16)
                   | ((v.w >= 0.f ? 0x01u : 0xFFu) << 24);
        out[i] = p;
    }
    __shared__ float sh[8];
    #pragma unroll
    for (int o = 16; o > 0; o >>= 1) s += __shfl_down_sync(0xFFFFFFFFu, s, o);
    if ((threadIdx.x & 31) == 0) sh[threadIdx.x >> 5] = s;
    __syncthreads();
    if (threadIdx.x == 0) {
        float t = 0.f;
        #pragma unroll
        for (int w = 0; w < 8; w++) t += sh[w];
        partial[blockIdx.x] = t;
    }
}

__global__ void prep_x_kernel(const float4* __restrict__ in) {
    prep_body(in, reinterpret_cast<uint32_t*>(g_Xb), (M_DIM * K_DIM) / 4, g_partX);
}
__global__ void prep_w_kernel(const float4* __restrict__ in) {
    prep_body(in, reinterpret_cast<uint32_t*>(g_Wb), (N_DIM * K_DIM) / 4, g_partW);
}

__global__ void finalize_kernel() {
    __shared__ float sh[256];
    int tid = threadIdx.x;
    float sx = 0.f;
    for (int i = tid; i < 2048; i += 256) sx += g_partX[i];
    sh[tid] = sx;
    __syncthreads();
    for (int o = 128; o > 0; o >>= 1) {
        if (tid < o) sh[tid] += sh[tid + o];
        __syncthreads();
    }
    float totx = sh[0];
    __syncthreads();
    float sw = 0.f;
    for (int i = tid; i < 1024; i += 256) sw += g_partW[i];
    sh[tid] = sw;
    __syncthreads();
    for (int o = 128; o > 0; o >>= 1) {
        if (tid < o) sh[tid] += sh[tid + o];
        __syncthreads();
    }
    if (tid == 0) {
        float ax = totx / ((float)M_DIM * (float)K_DIM);
        float aw = sh[0] / ((float)N_DIM * (float)K_DIM);
        g_scale = ax * aw;
    }
}

// ============================================================================
// Phase 2: IMMA GEMM, CTA 128x128, warp 64x32, 4-stage cp.async ring
// ============================================================================
__device__ __forceinline__ void fill_stage(uint32_t stage_base,
                                           const int8_t* __restrict__ Ag,
                                           const int8_t* __restrict__ Bg,
                                           int tid) {
    // A: 128 rows x 4 granules of 16B = 512 cp16; 256 threads -> 2 each
    #pragma unroll
    for (int t = 0; t < 2; t++) {
        int idx = tid + t * 256;
        int r = idx >> 2, g = idx & 3;
        cp16(stage_base + (uint32_t)(r * ASTRIDE + g * 16),
             Ag + (size_t)r * K_DIM + g * 16);
    }
    #pragma unroll
    for (int t = 0; t < 2; t++) {
        int idx = tid + t * 256;
        int r = idx >> 2, g = idx & 3;
        cp16(stage_base + A_SM_BYTES + (uint32_t)(r * ASTRIDE + g * 16),
             Bg + (size_t)r * K_DIM + g * 16);
    }
}

__global__ void __launch_bounds__(256, 2)
gemm_kernel(const float* __restrict__ bias, float* __restrict__ out) {
    extern __shared__ char smem[];
    const uint32_t smem_base = smem_u32(smem);
    const int tid = threadIdx.x;
    const int wid = tid >> 5;
    const int lane = tid & 31;
    const int g = lane >> 2;          // mma group id (0..7)
    const int tig = lane & 3;         // thread in group

    const int warp_m = wid & 1;       // 2 x 64-row blocks
    const int warp_n = wid >> 1;      // 4 x 32-col blocks

    // raster: n-tiles fastest so concurrent CTAs share A row-blocks in L2
    const int n0 = (blockIdx.x & 31) * BN;
    const int m0 = (blockIdx.x >> 5) * BM;

    const int8_t* Abase = g_Xb + (size_t)m0 * K_DIM;
    const int8_t* Bbase = g_Wb + (size_t)n0 * K_DIM;

    int acc[4][4][4];
    #pragma unroll
    for (int i = 0; i < 4; i++)
        #pragma unroll
        for (int j = 0; j < 4; j++)
            #pragma unroll
            for (int q = 0; q < 4; q++) acc[i][j][q] = 0;

    // prologue: fill chunks 0..DEPTH-2
    #pragma unroll
    for (int p = 0; p < DEPTH - 1; p++) {
        fill_stage(smem_base + p * STAGE_BYTES,
                   Abase + (size_t)p * BK, Bbase + (size_t)p * BK, tid);
        cp_commit();
    }

    // per-thread fragment base offsets (within a stage)
    const uint32_t a_off = (uint32_t)((warp_m * 64 + g) * ASTRIDE + tig * 4);
    const uint32_t b_off = (uint32_t)(A_SM_BYTES + (warp_n * 32 + g) * ASTRIDE + tig * 4);

    for (int c = 0; c < NCHUNK; c++) {
        // fill chunk c+DEPTH-1 into the stage freed last iteration
        {
            const int fc = c + DEPTH - 1;
            if (fc < NCHUNK) {
                fill_stage(smem_base + (fc % DEPTH) * STAGE_BYTES,
                           Abase + (size_t)fc * BK, Bbase + (size_t)fc * BK, tid);
            }
            cp_commit();   // always commit -> uniform pending count
        }
        cp_wait<DEPTH - 1>();   // chunk c resident
        __syncthreads();

        const uint32_t SA = smem_base + (uint32_t)((c % DEPTH) * STAGE_BYTES);
        #pragma unroll
        for (int kt = 0; kt < 2; kt++) {
            uint32_t a[4][4], b[4][2];
            #pragma unroll
            for (int mt = 0; mt < 4; mt++) {
                uint32_t base = SA + a_off + (uint32_t)(mt * 16 * ASTRIDE + kt * 32);
                a[mt][0] = lds32(base);
                a[mt][1] = lds32(base + 8 * ASTRIDE);
                a[mt][2] = lds32(base + 16);
                a[mt][3] = lds32(base + 8 * ASTRIDE + 16);
            }
            #pragma unroll
            for (int nt = 0; nt < 4; nt++) {
                uint32_t base = SA + b_off + (uint32_t)(nt * 8 * ASTRIDE + kt * 32);
                b[nt][0] = lds32(base);
                b[nt][1] = lds32(base + 16);
            }
            #pragma unroll
            for (int mt = 0; mt < 4; mt++)
                #pragma unroll
                for (int nt = 0; nt < 4; nt++)
                    imma16832(acc[mt][nt], a[mt], b[nt]);
        }
        __syncthreads();   // protect stage before next-iteration refill
    }

    // epilogue: scale + bias, float2 stores
    const float scale = g_scale;
    #pragma unroll
    for (int mt = 0; mt < 4; mt++) {
        const int r0 = m0 + warp_m * 64 + mt * 16 + g;
        const int r1 = r0 + 8;
        #pragma unroll
        for (int nt = 0; nt < 4; nt++) {
            const int col = n0 + warp_n * 32 + nt * 8 + tig * 2;
            const float2 bv = *reinterpret_cast<const float2*>(bias + col);
            float2 o0, o1;
            o0.x = (float)acc[mt][nt][0] * scale + bv.x;
            o0.y = (float)acc[mt][nt][1] * scale + bv.y;
            o1.x = (float)acc[mt][nt][2] * scale + bv.x;
            o1.y = (float)acc[mt][nt][3] * scale + bv.y;
            *reinterpret_cast<float2*>(out + (size_t)r0 * N_DIM + col) = o0;
            *reinterpret_cast<float2*>(out + (size_t)r1 * N_DIM + col) = o1;
        }
    }
}

// ============================================================================
// launch
// ============================================================================
extern "C" void kernel_launch(void* const* d_in, const int* in_sizes, int n_in,
                              void* d_out, int out_size) {
    const float* x    = (const float*)d_in[0];
    const float* w    = (const float*)d_in[1];
    const float* bias = (const float*)d_in[2];
    float* out = (float*)d_out;

    cudaFuncSetAttribute(gemm_kernel, cudaFuncAttributeMaxDynamicSharedMemorySize,
                         SMEM_TOTAL);

    prep_x_kernel<<<2048, 256>>>((const float4*)x);
    prep_w_kernel<<<1024, 256>>>((const float4*)w);
    finalize_kernel<<<1, 256>>>();
    gemm_kernel<<<(M_DIM / BM) * (N_DIM / BN), 256, SMEM_TOTAL>>>(bias, out);
}

// round 8
// speedup vs baseline: 1.1870x; 1.1870x over previous
#include <cuda_runtime.h>
#include <stdint.h>

// ============================================================================
// BinaryLinear: out = (mean|x| * mean|w|) * sign(x) @ sign(w)^T + bias
//   M=8192, N=4096, K=4096 (fp32 in/out)
// v8 (= v7/v6 resubmit; container infra flake, kernel never reached nvcc):
// int8 +/-1 binarize, IMMA m16n8k32 s8 GEMM (exact s32 accumulation),
// ldmatrix.x4 fragment loads, single __syncthreads per chunk, 4-stage
// cp.async ring, 80B-padded conflict-free smem.
// ============================================================================

#define M_DIM 8192
#define N_DIM 4096
#define K_DIM 4096

#define BM 128
#define BN 128
#define BK 64                        // int8 K elements per pipeline chunk
#define NCHUNK (K_DIM / BK)          // 64
#define DEPTH 4

#define ASTRIDE 80                   // bytes per 64B row, padded (bank-conflict-free)
#define A_SM_BYTES (BM * ASTRIDE)    // 10240
#define B_SM_BYTES (BN * ASTRIDE)    // 10240
#define STAGE_BYTES (A_SM_BYTES + B_SM_BYTES)   // 20480
#define SMEM_TOTAL (DEPTH * STAGE_BYTES)        // 81920

// ---- device scratch ----
__device__ int8_t g_Xb[(size_t)M_DIM * K_DIM];   // 32 MB
__device__ int8_t g_Wb[(size_t)N_DIM * K_DIM];   // 16 MB
__device__ float g_partX[2048];
__device__ float g_partW[1024];
__device__ float g_scale;

// ---- helpers ----
__device__ __forceinline__ uint32_t smem_u32(const void* p) {
    uint32_t a;
    asm("{ .reg .u64 t; cvta.to.shared.u64 t, %1; cvt.u32.u64 %0, t; }"
        : "=r"(a) : "l"(p));
    return a;
}

__device__ __forceinline__ void cp16(uint32_t saddr, const void* gaddr) {
    asm volatile("cp.async.cg.shared.global [%0], [%1], 16;\n"
                 :: "r"(saddr), "l"(gaddr));
}
__device__ __forceinline__ void cp_commit() {
    asm volatile("cp.async.commit_group;\n" ::);
}
template <int N>
__device__ __forceinline__ void cp_wait() {
    asm volatile("cp.async.wait_group %0;\n" :: "n"(N));
}

// ldmatrix x4: four 8x8 b16 tiles (8 rows x 16B each); lane l supplies the
// address of row (l&7) of tile (l>>3).
__device__ __forceinline__ void ldsm_x4(uint32_t* r, uint32_t addr) {
    asm volatile("ldmatrix.sync.aligned.m8n8.x4.shared.b16 {%0,%1,%2,%3}, [%4];"
                 : "=r"(r[0]), "=r"(r[1]), "=r"(r[2]), "=r"(r[3]) : "r"(addr));
}

// s8 x s8 -> s32 : D(16x8) += A(16x32) * B(32x8)
__device__ __forceinline__ void imma16832(int* c, const uint32_t* a,
                                          uint32_t b0, uint32_t b1) {
    asm volatile(
        "mma.sync.aligned.m16n8k32.row.col.s32.s8.s8.s32 "
        "{%0,%1,%2,%3}, {%4,%5,%6,%7}, {%8,%9}, {%0,%1,%2,%3};"
        : "+r"(c[0]), "+r"(c[1]), "+r"(c[2]), "+r"(c[3])
        : "r"(a[0]), "r"(a[1]), "r"(a[2]), "r"(a[3]),
          "r"(b0), "r"(b1));
}

// ============================================================================
// Phase 1: binarize fp32 -> int8 {-1,+1}, deterministic |.| partial sums
// ============================================================================
__device__ __forceinline__ void prep_body(const float4* __restrict__ in,
                                          uint32_t* __restrict__ out,
                                          int n4, float* __restrict__ partial) {
    float s = 0.f;
    const int stride = gridDim.x * blockDim.x;
    for (int i = blockIdx.x * blockDim.x + threadIdx.x; i < n4; i += stride) {
        float4 v = in[i];
        s += fabsf(v.x) + fabsf(v.y) + fabsf(v.z) + fabsf(v.w);
        uint32_t p = (v.x >= 0.f ? 0x01u : 0xFFu)
                   | ((v.y >= 0.f ? 0x01u : 0xFFu) << 8)
                   | ((v.z >= 0.f ? 0x01u : 0xFFu) << 16)
                   | ((v.w >= 0.f ? 0x01u : 0xFFu) << 24);
        out[i] = p;
    }
    __shared__ float sh[8];
    #pragma unroll
    for (int o = 16; o > 0; o >>= 1) s += __shfl_down_sync(0xFFFFFFFFu, s, o);
    if ((threadIdx.x & 31) == 0) sh[threadIdx.x >> 5] = s;
    __syncthreads();
    if (threadIdx.x == 0) {
        float t = 0.f;
        #pragma unroll
        for (int w = 0; w < 8; w++) t += sh[w];
        partial[blockIdx.x] = t;
    }
}

__global__ void prep_x_kernel(const float4* __restrict__ in) {
    prep_body(in, reinterpret_cast<uint32_t*>(g_Xb), (M_DIM * K_DIM) / 4, g_partX);
}
__global__ void prep_w_kernel(const float4* __restrict__ in) {
    prep_body(in, reinterpret_cast<uint32_t*>(g_Wb), (N_DIM * K_DIM) / 4, g_partW);
}

__global__ void finalize_kernel() {
    __shared__ float sh[256];
    int tid = threadIdx.x;
    float sx = 0.f;
    for (int i = tid; i < 2048; i += 256) sx += g_partX[i];
    sh[tid] = sx;
    __syncthreads();
    for (int o = 128; o > 0; o >>= 1) {
        if (tid < o) sh[tid] += sh[tid + o];
        __syncthreads();
    }
    float totx = sh[0];
    __syncthreads();
    float sw = 0.f;
    for (int i = tid; i < 1024; i += 256) sw += g_partW[i];
    sh[tid] = sw;
    __syncthreads();
    for (int o = 128; o > 0; o >>= 1) {
        if (tid < o) sh[tid] += sh[tid + o];
        __syncthreads();
    }
    if (tid == 0) {
        float ax = totx / ((float)M_DIM * (float)K_DIM);
        float aw = sh[0] / ((float)N_DIM * (float)K_DIM);
        g_scale = ax * aw;
    }
}

// ============================================================================
// Phase 2: IMMA GEMM, CTA 128x128, warp 64x32, 4-stage cp.async ring,
// ldmatrix fragment loads, one barrier per chunk.
// ============================================================================
__device__ __forceinline__ void fill_stage(uint32_t stage_base,
                                           const int8_t* __restrict__ Ag,
                                           const int8_t* __restrict__ Bg,
                                           int tid) {
    #pragma unroll
    for (int t = 0; t < 2; t++) {
        int idx = tid + t * 256;
        int r = idx >> 2, g = idx & 3;
        cp16(stage_base + (uint32_t)(r * ASTRIDE + g * 16),
             Ag + (size_t)r * K_DIM + g * 16);
    }
    #pragma unroll
    for (int t = 0; t < 2; t++) {
        int idx = tid + t * 256;
        int r = idx >> 2, g = idx & 3;
        cp16(stage_base + A_SM_BYTES + (uint32_t)(r * ASTRIDE + g * 16),
             Bg + (size_t)r * K_DIM + g * 16);
    }
}

__global__ void __launch_bounds__(256, 2)
gemm_kernel(const float* __restrict__ bias, float* __restrict__ out) {
    extern __shared__ char smem[];
    const uint32_t smem_base = smem_u32(smem);
    const int tid = threadIdx.x;
    const int wid = tid >> 5;
    const int lane = tid & 31;
    const int g = lane >> 2;          // mma group id (0..7)
    const int tig = lane & 3;         // thread in group

    const int warp_m = wid & 1;       // 2 x 64-row blocks
    const int warp_n = wid >> 1;      // 4 x 32-col blocks

    // raster: n-tiles fastest so concurrent CTAs share A row-blocks in L2
    const int n0 = (blockIdx.x & 31) * BN;
    const int m0 = (blockIdx.x >> 5) * BM;

    const int8_t* Abase = g_Xb + (size_t)m0 * K_DIM;
    const int8_t* Bbase = g_Wb + (size_t)n0 * K_DIM;

    int acc[4][4][4];
    #pragma unroll
    for (int i = 0; i < 4; i++)
        #pragma unroll
        for (int j = 0; j < 4; j++)
            #pragma unroll
            for (int q = 0; q < 4; q++) acc[i][j][q] = 0;

    // prologue: fill chunks 0..DEPTH-2
    #pragma unroll
    for (int p = 0; p < DEPTH - 1; p++) {
        fill_stage(smem_base + p * STAGE_BYTES,
                   Abase + (size_t)p * BK, Bbase + (size_t)p * BK, tid);
        cp_commit();
    }

    // ---- ldmatrix per-lane base offsets (within a stage) ----
    // A tile (mt,kt): 16 rows x 32B = 4 8x8b16 tiles, reg order
    //   {rows0-7/b0-15, rows8-15/b0-15, rows0-7/b16-31, rows8-15/b16-31}
    const int a_row = warp_m * 64 + (lane & 7) + ((lane >> 3) & 1) * 8;
    const uint32_t a_off = (uint32_t)(a_row * ASTRIDE + (lane >> 4) * 16);
    // B pair p covers nt=2p,2p+1: regs {b[2p][0], b[2p][1], b[2p+1][0], b[2p+1][1]}
    const int b_row = warp_n * 32 + ((lane >> 4) * 8) + (lane & 7);
    const uint32_t b_off = (uint32_t)(A_SM_BYTES + b_row * ASTRIDE
                                      + (((lane >> 3) & 1) * 16));

    for (int c = 0; c < NCHUNK; c++) {
        cp_wait<DEPTH - 2>();     // chunk c resident (uniform commit count)
        __syncthreads();          // all threads done with stage (c-1)%DEPTH

        // fill chunk c+DEPTH-1 into stage (c-1)%DEPTH (freed by the barrier)
        {
            const int fc = c + DEPTH - 1;
            if (fc < NCHUNK) {
                fill_stage(smem_base + (fc % DEPTH) * STAGE_BYTES,
                           Abase + (size_t)fc * BK, Bbase + (size_t)fc * BK, tid);
            }
            cp_commit();          // always commit -> uniform pending count
        }

        const uint32_t SA = smem_base + (uint32_t)((c % DEPTH) * STAGE_BYTES);
        #pragma unroll
        for (int kt = 0; kt < 2; kt++) {
            uint32_t a[4][4], b[2][4];
            #pragma unroll
            for (int mt = 0; mt < 4; mt++)
                ldsm_x4(a[mt], SA + a_off + (uint32_t)(mt * 16 * ASTRIDE + kt * 32));
            #pragma unroll
            for (int p = 0; p < 2; p++)
                ldsm_x4(b[p], SA + b_off + (uint32_t)(p * 16 * ASTRIDE + kt * 32));
            #pragma unroll
            for (int mt = 0; mt < 4; mt++)
                #pragma unroll
                for (int nt = 0; nt < 4; nt++)
                    imma16832(acc[mt][nt], a[mt],
                              b[nt >> 1][(nt & 1) * 2], b[nt >> 1][(nt & 1) * 2 + 1]);
        }
    }

    // epilogue: scale + bias, float2 stores
    const float scale = g_scale;
    #pragma unroll
    for (int mt = 0; mt < 4; mt++) {
        const int r0 = m0 + warp_m * 64 + mt * 16 + g;
        const int r1 = r0 + 8;
        #pragma unroll
        for (int nt = 0; nt < 4; nt++) {
            const int col = n0 + warp_n * 32 + nt * 8 + tig * 2;
            const float2 bv = *reinterpret_cast<const float2*>(bias + col);
            float2 o0, o1;
            o0.x = (float)acc[mt][nt][0] * scale + bv.x;
            o0.y = (float)acc[mt][nt][1] * scale + bv.y;
            o1.x = (float)acc[mt][nt][2] * scale + bv.x;
            o1.y = (float)acc[mt][nt][3] * scale + bv.y;
            *reinterpret_cast<float2*>(out + (size_t)r0 * N_DIM + col) = o0;
            *reinterpret_cast<float2*>(out + (size_t)r1 * N_DIM + col) = o1;
        }
    }
}

// ============================================================================
// launch
// ============================================================================
extern "C" void kernel_launch(void* const* d_in, const int* in_sizes, int n_in,
                              void* d_out, int out_size) {
    const float* x    = (const float*)d_in[0];
    const float* w    = (const float*)d_in[1];
    const float* bias = (const float*)d_in[2];
    float* out = (float*)d_out;

    cudaFuncSetAttribute(gemm_kernel, cudaFuncAttributeMaxDynamicSharedMemorySize,
                         SMEM_TOTAL);

    prep_x_kernel<<<2048, 256>>>((const float4*)x);
    prep_w_kernel<<<1024, 256>>>((const float4*)w);
    finalize_kernel<<<1, 256>>>();
    gemm_kernel<<<(M_DIM / BM) * (N_DIM / BN), 256, SMEM_TOTAL>>>(bias, out);
}

// round 10
// speedup vs baseline: 1.3048x; 1.0992x over previous
#include <cuda_runtime.h>
#include <stdint.h>

// ============================================================================
// BinaryLinear: out = (mean|x| * mean|w|) * sign(x) @ sign(w)^T + bias
//   M=8192, N=4096, K=4096 (fp32 in/out)
// v10 (= v9 resubmit; container infra flake, kernel never reached nvcc):
// int8 +/-1 binarize, IMMA m16n8k32 s8 GEMM (exact s32 accumulation),
// ldmatrix.x4 fragment loads, BK=128 chunks, DEPTH=3 cp.async ring
// (32 rendezvous vs v8's 64), 144B-padded conflict-free smem.
// ============================================================================

#define M_DIM 8192
#define N_DIM 4096
#define K_DIM 4096

#define BM 128
#define BN 128
#define BK 128                       // int8 K elements per pipeline chunk
#define NCHUNK (K_DIM / BK)          // 32
#define DEPTH 3

#define ASTRIDE 144                  // bytes per 128B row, padded (conflict-free)
#define A_SM_BYTES (BM * ASTRIDE)    // 18432
#define B_SM_BYTES (BN * ASTRIDE)    // 18432
#define STAGE_BYTES (A_SM_BYTES + B_SM_BYTES)   // 36864
#define SMEM_TOTAL (DEPTH * STAGE_BYTES)        // 110592

// ---- device scratch ----
__device__ int8_t g_Xb[(size_t)M_DIM * K_DIM];   // 32 MB
__device__ int8_t g_Wb[(size_t)N_DIM * K_DIM];   // 16 MB
__device__ float g_partX[2048];
__device__ float g_partW[1024];
__device__ float g_scale;

// ---- helpers ----
__device__ __forceinline__ uint32_t smem_u32(const void* p) {
    uint32_t a;
    asm("{ .reg .u64 t; cvta.to.shared.u64 t, %1; cvt.u32.u64 %0, t; }"
        : "=r"(a) : "l"(p));
    return a;
}

__device__ __forceinline__ void cp16(uint32_t saddr, const void* gaddr) {
    asm volatile("cp.async.cg.shared.global [%0], [%1], 16;\n"
                 :: "r"(saddr), "l"(gaddr));
}
__device__ __forceinline__ void cp_commit() {
    asm volatile("cp.async.commit_group;\n" ::);
}
template <int N>
__device__ __forceinline__ void cp_wait() {
    asm volatile("cp.async.wait_group %0;\n" :: "n"(N));
}

// ldmatrix x4: four 8x8 b16 tiles (8 rows x 16B each); lane l supplies the
// address of row (l&7) of tile (l>>3).
__device__ __forceinline__ void ldsm_x4(uint32_t* r, uint32_t addr) {
    asm volatile("ldmatrix.sync.aligned.m8n8.x4.shared.b16 {%0,%1,%2,%3}, [%4];"
                 : "=r"(r[0]), "=r"(r[1]), "=r"(r[2]), "=r"(r[3]) : "r"(addr));
}

// s8 x s8 -> s32 : D(16x8) += A(16x32) * B(32x8)
__device__ __forceinline__ void imma16832(int* c, const uint32_t* a,
                                          uint32_t b0, uint32_t b1) {
    asm volatile(
        "mma.sync.aligned.m16n8k32.row.col.s32.s8.s8.s32 "
        "{%0,%1,%2,%3}, {%4,%5,%6,%7}, {%8,%9}, {%0,%1,%2,%3};"
        : "+r"(c[0]), "+r"(c[1]), "+r"(c[2]), "+r"(c[3])
        : "r"(a[0]), "r"(a[1]), "r"(a[2]), "r"(a[3]),
          "r"(b0), "r"(b1));
}

// ============================================================================
// Phase 1: binarize fp32 -> int8 {-1,+1}, deterministic |.| partial sums
// ============================================================================
__device__ __forceinline__ void prep_body(const float4* __restrict__ in,
                                          uint32_t* __restrict__ out,
                                          int n4, float* __restrict__ partial) {
    float s = 0.f;
    const int stride = gridDim.x * blockDim.x;
    for (int i = blockIdx.x * blockDim.x + threadIdx.x; i < n4; i += stride) {
        float4 v = in[i];
        s += fabsf(v.x) + fabsf(v.y) + fabsf(v.z) + fabsf(v.w);
        uint32_t p = (v.x >= 0.f ? 0x01u : 0xFFu)
                   | ((v.y >= 0.f ? 0x01u : 0xFFu) << 8)
                   | ((v.z >= 0.f ? 0x01u : 0xFFu) << 16)
                   | ((v.w >= 0.f ? 0x01u : 0xFFu) << 24);
        out[i] = p;
    }
    __shared__ float sh[8];
    #pragma unroll
    for (int o = 16; o > 0; o >>= 1) s += __shfl_down_sync(0xFFFFFFFFu, s, o);
    if ((threadIdx.x & 31) == 0) sh[threadIdx.x >> 5] = s;
    __syncthreads();
    if (threadIdx.x == 0) {
        float t = 0.f;
        #pragma unroll
        for (int w = 0; w < 8; w++) t += sh[w];
        partial[blockIdx.x] = t;
    }
}

__global__ void prep_x_kernel(const float4* __restrict__ in) {
    prep_body(in, reinterpret_cast<uint32_t*>(g_Xb), (M_DIM * K_DIM) / 4, g_partX);
}
__global__ void prep_w_kernel(const float4* __restrict__ in) {
    prep_body(in, reinterpret_cast<uint32_t*>(g_Wb), (N_DIM * K_DIM) / 4, g_partW);
}

__global__ void finalize_kernel() {
    __shared__ float sh[256];
    int tid = threadIdx.x;
    float sx = 0.f;
    for (int i = tid; i < 2048; i += 256) sx += g_partX[i];
    sh[tid] = sx;
    __syncthreads();
    for (int o = 128; o > 0; o >>= 1) {
        if (tid < o) sh[tid] += sh[tid + o];
        __syncthreads();
    }
    float totx = sh[0];
    __syncthreads();
    float sw = 0.f;
    for (int i = tid; i < 1024; i += 256) sw += g_partW[i];
    sh[tid] = sw;
    __syncthreads();
    for (int o = 128; o > 0; o >>= 1) {
        if (tid < o) sh[tid] += sh[tid + o];
        __syncthreads();
    }
    if (tid == 0) {
        float ax = totx / ((float)M_DIM * (float)K_DIM);
        float aw = sh[0] / ((float)N_DIM * (float)K_DIM);
        g_scale = ax * aw;
    }
}

// ============================================================================
// Phase 2: IMMA GEMM, CTA 128x128, warp 64x32, 3-stage cp.async ring,
// BK=128 chunks, ldmatrix fragment loads, one barrier per chunk.
// ============================================================================
__device__ __forceinline__ void fill_stage(uint32_t stage_base,
                                           const int8_t* __restrict__ Ag,
                                           const int8_t* __restrict__ Bg,
                                           int tid) {
    // A: 128 rows x 8 granules of 16B = 1024 cp16; 256 threads -> 4 each
    #pragma unroll
    for (int t = 0; t < 4; t++) {
        int idx = tid + t * 256;
        int r = idx >> 3, g = idx & 7;
        cp16(stage_base + (uint32_t)(r * ASTRIDE + g * 16),
             Ag + (size_t)r * K_DIM + g * 16);
    }
    #pragma unroll
    for (int t = 0; t < 4; t++) {
        int idx = tid + t * 256;
        int r = idx >> 3, g = idx & 7;
        cp16(stage_base + A_SM_BYTES + (uint32_t)(r * ASTRIDE + g * 16),
             Bg + (size_t)r * K_DIM + g * 16);
    }
}

__global__ void __launch_bounds__(256, 2)
gemm_kernel(const float* __restrict__ bias, float* __restrict__ out) {
    extern __shared__ char smem[];
    const uint32_t smem_base = smem_u32(smem);
    const int tid = threadIdx.x;
    const int wid = tid >> 5;
    const int lane = tid & 31;
    const int g = lane >> 2;          // mma group id (0..7)
    const int tig = lane & 3;         // thread in group

    const int warp_m = wid & 1;       // 2 x 64-row blocks
    const int warp_n = wid >> 1;      // 4 x 32-col blocks

    // raster: n-tiles fastest so concurrent CTAs share A row-blocks in L2
    const int n0 = (blockIdx.x & 31) * BN;
    const int m0 = (blockIdx.x >> 5) * BM;

    const int8_t* Abase = g_Xb + (size_t)m0 * K_DIM;
    const int8_t* Bbase = g_Wb + (size_t)n0 * K_DIM;

    int acc[4][4][4];
    #pragma unroll
    for (int i = 0; i < 4; i++)
        #pragma unroll
        for (int j = 0; j < 4; j++)
            #pragma unroll
            for (int q = 0; q < 4; q++) acc[i][j][q] = 0;

    // prologue: fill chunks 0..DEPTH-2
    #pragma unroll
    for (int p = 0; p < DEPTH - 1; p++) {
        fill_stage(smem_base + p * STAGE_BYTES,
                   Abase + (size_t)p * BK, Bbase + (size_t)p * BK, tid);
        cp_commit();
    }

    // ---- ldmatrix per-lane base offsets (within a stage) ----
    // A tile (mt,kt): 16 rows x 32B = 4 8x8b16 tiles, reg order
    //   {rows0-7/b0-15, rows8-15/b0-15, rows0-7/b16-31, rows8-15/b16-31}
    const int a_row = warp_m * 64 + (lane & 7) + ((lane >> 3) & 1) * 8;
    const uint32_t a_off = (uint32_t)(a_row * ASTRIDE + (lane >> 4) * 16);
    // B pair p covers nt=2p,2p+1: regs {b[2p][0], b[2p][1], b[2p+1][0], b[2p+1][1]}
    const int b_row = warp_n * 32 + ((lane >> 4) * 8) + (lane & 7);
    const uint32_t b_off = (uint32_t)(A_SM_BYTES + b_row * ASTRIDE
                                      + (((lane >> 3) & 1) * 16));

    for (int c = 0; c < NCHUNK; c++) {
        cp_wait<DEPTH - 2>();     // chunk c resident (uniform commit count)
        __syncthreads();          // all threads done with stage (c-1)%DEPTH

        // fill chunk c+DEPTH-1 into stage (c-1)%DEPTH (freed by the barrier)
        {
            const int fc = c + DEPTH - 1;
            if (fc < NCHUNK) {
                fill_stage(smem_base + (fc % DEPTH) * STAGE_BYTES,
                           Abase + (size_t)fc * BK, Bbase + (size_t)fc * BK, tid);
            }
            cp_commit();          // always commit -> uniform pending count
        }

        const uint32_t SA = smem_base + (uint32_t)((c % DEPTH) * STAGE_BYTES);
        #pragma unroll
        for (int kt = 0; kt < 4; kt++) {           // 4 x 32B K-steps per chunk
            uint32_t a[4][4], b[2][4];
            #pragma unroll
            for (int mt = 0; mt < 4; mt++)
                ldsm_x4(a[mt], SA + a_off + (uint32_t)(mt * 16 * ASTRIDE + kt * 32));
            #pragma unroll
            for (int p = 0; p < 2; p++)
                ldsm_x4(b[p], SA + b_off + (uint32_t)(p * 16 * ASTRIDE + kt * 32));
            #pragma unroll
            for (int mt = 0; mt < 4; mt++)
                #pragma unroll
                for (int nt = 0; nt < 4; nt++)
                    imma16832(acc[mt][nt], a[mt],
                              b[nt >> 1][(nt & 1) * 2], b[nt >> 1][(nt & 1) * 2 + 1]);
        }
    }

    // epilogue: scale + bias, float2 stores
    const float scale = g_scale;
    #pragma unroll
    for (int mt = 0; mt < 4; mt++) {
        const int r0 = m0 + warp_m * 64 + mt * 16 + g;
        const int r1 = r0 + 8;
        #pragma unroll
        for (int nt = 0; nt < 4; nt++) {
            const int col = n0 + warp_n * 32 + nt * 8 + tig * 2;
            const float2 bv = *reinterpret_cast<const float2*>(bias + col);
            float2 o0, o1;
            o0.x = (float)acc[mt][nt][0] * scale + bv.x;
            o0.y = (float)acc[mt][nt][1] * scale + bv.y;
            o1.x = (float)acc[mt][nt][2] * scale + bv.x;
            o1.y = (float)acc[mt][nt][3] * scale + bv.y;
            *reinterpret_cast<float2*>(out + (size_t)r0 * N_DIM + col) = o0;
            *reinterpret_cast<float2*>(out + (size_t)r1 * N_DIM + col) = o1;
        }
    }
}

// ============================================================================
// launch
// ============================================================================
extern "C" void kernel_launch(void* const* d_in, const int* in_sizes, int n_in,
                              void* d_out, int out_size) {
    const float* x    = (const float*)d_in[0];
    const float* w    = (const float*)d_in[1];
    const float* bias = (const float*)d_in[2];
    float* out = (float*)d_out;

    cudaFuncSetAttribute(gemm_kernel, cudaFuncAttributeMaxDynamicSharedMemorySize,
                         SMEM_TOTAL);

    prep_x_kernel<<<2048, 256>>>((const float4*)x);
    prep_w_kernel<<<1024, 256>>>((const float4*)w);
    finalize_kernel<<<1, 256>>>();
    gemm_kernel<<<(M_DIM / BM) * (N_DIM / BN), 256, SMEM_TOTAL>>>(bias, out);
}

// round 12
// speedup vs baseline: 1.4023x; 1.0748x over previous
#include <cuda_runtime.h>
#include <stdint.h>

// ============================================================================
// BinaryLinear: out = (mean|x| * mean|w|) * sign(x) @ sign(w)^T + bias
//   M=8192, N=4096, K=4096 (fp32 in/out)
// v12 (= v11 resubmit; container infra flake, kernel never reached nvcc):
// int8 +/-1 binarize, IMMA m16n8k32 s8 GEMM, ldmatrix.x4, BK=128, DEPTH=3
// cp.async ring, rolling A-fragment pipeline, fill deferred past kt=0.
// ============================================================================

#define M_DIM 8192
#define N_DIM 4096
#define K_DIM 4096

#define BM 128
#define BN 128
#define BK 128                       // int8 K elements per pipeline chunk
#define NCHUNK (K_DIM / BK)          // 32
#define DEPTH 3

#define ASTRIDE 144                  // bytes per 128B row, padded (conflict-free)
#define A_SM_BYTES (BM * ASTRIDE)    // 18432
#define B_SM_BYTES (BN * ASTRIDE)    // 18432
#define STAGE_BYTES (A_SM_BYTES + B_SM_BYTES)   // 36864
#define SMEM_TOTAL (DEPTH * STAGE_BYTES)        // 110592

// ---- device scratch ----
__device__ int8_t g_Xb[(size_t)M_DIM * K_DIM];   // 32 MB
__device__ int8_t g_Wb[(size_t)N_DIM * K_DIM];   // 16 MB
__device__ float g_partX[2048];
__device__ float g_partW[1024];
__device__ float g_scale;

// ---- helpers ----
__device__ __forceinline__ uint32_t smem_u32(const void* p) {
    uint32_t a;
    asm("{ .reg .u64 t; cvta.to.shared.u64 t, %1; cvt.u32.u64 %0, t; }"
        : "=r"(a) : "l"(p));
    return a;
}

__device__ __forceinline__ void cp16(uint32_t saddr, const void* gaddr) {
    asm volatile("cp.async.cg.shared.global [%0], [%1], 16;\n"
                 :: "r"(saddr), "l"(gaddr));
}
__device__ __forceinline__ void cp_commit() {
    asm volatile("cp.async.commit_group;\n" ::);
}
template <int N>
__device__ __forceinline__ void cp_wait() {
    asm volatile("cp.async.wait_group %0;\n" :: "n"(N));
}

// ldmatrix x4: four 8x8 b16 tiles (8 rows x 16B each); lane l supplies the
// address of row (l&7) of tile (l>>3).
__device__ __forceinline__ void ldsm_x4(uint32_t* r, uint32_t addr) {
    asm volatile("ldmatrix.sync.aligned.m8n8.x4.shared.b16 {%0,%1,%2,%3}, [%4];"
                 : "=r"(r[0]), "=r"(r[1]), "=r"(r[2]), "=r"(r[3]) : "r"(addr));
}

// s8 x s8 -> s32 : D(16x8) += A(16x32) * B(32x8)
__device__ __forceinline__ void imma16832(int* c, const uint32_t* a,
                                          uint32_t b0, uint32_t b1) {
    asm volatile(
        "mma.sync.aligned.m16n8k32.row.col.s32.s8.s8.s32 "
        "{%0,%1,%2,%3}, {%4,%5,%6,%7}, {%8,%9}, {%0,%1,%2,%3};"
        : "+r"(c[0]), "+r"(c[1]), "+r"(c[2]), "+r"(c[3])
        : "r"(a[0]), "r"(a[1]), "r"(a[2]), "r"(a[3]),
          "r"(b0), "r"(b1));
}

// ============================================================================
// Phase 1: binarize fp32 -> int8 {-1,+1}, deterministic |.| partial sums
// ============================================================================
__device__ __forceinline__ void prep_body(const float4* __restrict__ in,
                                          uint32_t* __restrict__ out,
                                          int n4, float* __restrict__ partial) {
    float s = 0.f;
    const int stride = gridDim.x * blockDim.x;
    for (int i = blockIdx.x * blockDim.x + threadIdx.x; i < n4; i += stride) {
        float4 v = in[i];
        s += fabsf(v.x) + fabsf(v.y) + fabsf(v.z) + fabsf(v.w);
        uint32_t p = (v.x >= 0.f ? 0x01u : 0xFFu)
                   | ((v.y >= 0.f ? 0x01u : 0xFFu) << 8)
                   | ((v.z >= 0.f ? 0x01u : 0xFFu) << 16)
                   | ((v.w >= 0.f ? 0x01u : 0xFFu) << 24);
        out[i] = p;
    }
    __shared__ float sh[8];
    #pragma unroll
    for (int o = 16; o > 0; o >>= 1) s += __shfl_down_sync(0xFFFFFFFFu, s, o);
    if ((threadIdx.x & 31) == 0) sh[threadIdx.x >> 5] = s;
    __syncthreads();
    if (threadIdx.x == 0) {
        float t = 0.f;
        #pragma unroll
        for (int w = 0; w < 8; w++) t += sh[w];
        partial[blockIdx.x] = t;
    }
}

__global__ void prep_x_kernel(const float4* __restrict__ in) {
    prep_body(in, reinterpret_cast<uint32_t*>(g_Xb), (M_DIM * K_DIM) / 4, g_partX);
}
__global__ void prep_w_kernel(const float4* __restrict__ in) {
    prep_body(in, reinterpret_cast<uint32_t*>(g_Wb), (N_DIM * K_DIM) / 4, g_partW);
}

__global__ void finalize_kernel() {
    __shared__ float sh[256];
    int tid = threadIdx.x;
    float sx = 0.f;
    for (int i = tid; i < 2048; i += 256) sx += g_partX[i];
    sh[tid] = sx;
    __syncthreads();
    for (int o = 128; o > 0; o >>= 1) {
        if (tid < o) sh[tid] += sh[tid + o];
        __syncthreads();
    }
    float totx = sh[0];
    __syncthreads();
    float sw = 0.f;
    for (int i = tid; i < 1024; i += 256) sw += g_partW[i];
    sh[tid] = sw;
    __syncthreads();
    for (int o = 128; o > 0; o >>= 1) {
        if (tid < o) sh[tid] += sh[tid + o];
        __syncthreads();
    }
    if (tid == 0) {
        float ax = totx / ((float)M_DIM * (float)K_DIM);
        float aw = sh[0] / ((float)N_DIM * (float)K_DIM);
        g_scale = ax * aw;
    }
}

// ============================================================================
// Phase 2: IMMA GEMM, CTA 128x128, warp 64x32, 3-stage cp.async ring,
// BK=128 chunks, rolling-fragment ldmatrix pipeline, one barrier per chunk.
// ============================================================================
__device__ __forceinline__ void fill_stage(uint32_t stage_base,
                                           const int8_t* __restrict__ Ag,
                                           const int8_t* __restrict__ Bg,
                                           int tid) {
    // A: 128 rows x 8 granules of 16B = 1024 cp16; 256 threads -> 4 each
    #pragma unroll
    for (int t = 0; t < 4; t++) {
        int idx = tid + t * 256;
        int r = idx >> 3, g = idx & 7;
        cp16(stage_base + (uint32_t)(r * ASTRIDE + g * 16),
             Ag + (size_t)r * K_DIM + g * 16);
    }
    #pragma unroll
    for (int t = 0; t < 4; t++) {
        int idx = tid + t * 256;
        int r = idx >> 3, g = idx & 7;
        cp16(stage_base + A_SM_BYTES + (uint32_t)(r * ASTRIDE + g * 16),
             Bg + (size_t)r * K_DIM + g * 16);
    }
}

__global__ void __launch_bounds__(256, 2)
gemm_kernel(const float* __restrict__ bias, float* __restrict__ out) {
    extern __shared__ char smem[];
    const uint32_t smem_base = smem_u32(smem);
    const int tid = threadIdx.x;
    const int wid = tid >> 5;
    const int lane = tid & 31;
    const int g = lane >> 2;          // mma group id (0..7)
    const int tig = lane & 3;         // thread in group

    const int warp_m = wid & 1;       // 2 x 64-row blocks
    const int warp_n = wid >> 1;      // 4 x 32-col blocks

    // raster: n-tiles fastest so concurrent CTAs share A row-blocks in L2
    const int n0 = (blockIdx.x & 31) * BN;
    const int m0 = (blockIdx.x >> 5) * BM;

    const int8_t* Abase = g_Xb + (size_t)m0 * K_DIM;
    const int8_t* Bbase = g_Wb + (size_t)n0 * K_DIM;

    int acc[4][4][4];
    #pragma unroll
    for (int i = 0; i < 4; i++)
        #pragma unroll
        for (int j = 0; j < 4; j++)
            #pragma unroll
            for (int q = 0; q < 4; q++) acc[i][j][q] = 0;

    // prologue: fill chunks 0..DEPTH-2
    #pragma unroll
    for (int p = 0; p < DEPTH - 1; p++) {
        fill_stage(smem_base + p * STAGE_BYTES,
                   Abase + (size_t)p * BK, Bbase + (size_t)p * BK, tid);
        cp_commit();
    }

    // ---- ldmatrix per-lane base offsets (within a stage) ----
    const int a_row = warp_m * 64 + (lane & 7) + ((lane >> 3) & 1) * 8;
    const uint32_t a_off = (uint32_t)(a_row * ASTRIDE + (lane >> 4) * 16);
    const int b_row = warp_n * 32 + ((lane >> 4) * 8) + (lane & 7);
    const uint32_t b_off = (uint32_t)(A_SM_BYTES + b_row * ASTRIDE
                                      + (((lane >> 3) & 1) * 16));

    for (int c = 0; c < NCHUNK; c++) {
        cp_wait<DEPTH - 2>();     // chunk c resident (uniform commit count)
        __syncthreads();          // all threads done with stage (c-1)%DEPTH

        const int fc = c + DEPTH - 1;       // chunk to fill this iteration
        const uint32_t SA = smem_base + (uint32_t)((c % DEPTH) * STAGE_BYTES);

        #pragma unroll
        for (int kt = 0; kt < 4; kt++) {    // 4 x 32B K-steps per chunk
            uint32_t b[2][4];
            uint32_t a[2][4];               // rolling A fragments
            #pragma unroll
            for (int p = 0; p < 2; p++)
                ldsm_x4(b[p], SA + b_off + (uint32_t)(p * 16 * ASTRIDE + kt * 32));
            ldsm_x4(a[0], SA + a_off + (uint32_t)(kt * 32));
            #pragma unroll
            for (int mt = 0; mt < 4; mt++) {
                if (mt < 3)
                    ldsm_x4(a[(mt + 1) & 1],
                            SA + a_off + (uint32_t)((mt + 1) * 16 * ASTRIDE + kt * 32));
                #pragma unroll
                for (int nt = 0; nt < 4; nt++)
                    imma16832(acc[mt][nt], a[mt & 1],
                              b[nt >> 1][(nt & 1) * 2], b[nt >> 1][(nt & 1) * 2 + 1]);
            }
            // defer fill until after kt=0: first IMMAs start immediately
            // after the barrier; cp.async issue overlaps kt>=1 compute.
            if (kt == 0) {
                if (fc < NCHUNK) {
                    fill_stage(smem_base + (fc % DEPTH) * STAGE_BYTES,
                               Abase + (size_t)fc * BK, Bbase + (size_t)fc * BK, tid);
                }
                cp_commit();      // always commit -> uniform pending count
            }
        }
    }

    // epilogue: scale + bias, float2 stores
    const float scale = g_scale;
    #pragma unroll
    for (int mt = 0; mt < 4; mt++) {
        const int r0 = m0 + warp_m * 64 + mt * 16 + g;
        const int r1 = r0 + 8;
        #pragma unroll
        for (int nt = 0; nt < 4; nt++) {
            const int col = n0 + warp_n * 32 + nt * 8 + tig * 2;
            const float2 bv = *reinterpret_cast<const float2*>(bias + col);
            float2 o0, o1;
            o0.x = (float)acc[mt][nt][0] * scale + bv.x;
            o0.y = (float)acc[mt][nt][1] * scale + bv.y;
            o1.x = (float)acc[mt][nt][2] * scale + bv.x;
            o1.y = (float)acc[mt][nt][3] * scale + bv.y;
            *reinterpret_cast<float2*>(out + (size_t)r0 * N_DIM + col) = o0;
            *reinterpret_cast<float2*>(out + (size_t)r1 * N_DIM + col) = o1;
        }
    }
}

// ============================================================================
// launch
// ============================================================================
extern "C" void kernel_launch(void* const* d_in, const int* in_sizes, int n_in,
                              void* d_out, int out_size) {
    const float* x    = (const float*)d_in[0];
    const float* w    = (const float*)d_in[1];
    const float* bias = (const float*)d_in[2];
    float* out = (float*)d_out;

    cudaFuncSetAttribute(gemm_kernel, cudaFuncAttributeMaxDynamicSharedMemorySize,
                         SMEM_TOTAL);

    prep_x_kernel<<<2048, 256>>>((const float4*)x);
    prep_w_kernel<<<1024, 256>>>((const float4*)w);
    finalize_kernel<<<1, 256>>>();
    gemm_kernel<<<(M_DIM / BM) * (N_DIM / BN), 256, SMEM_TOTAL>>>(bias, out);
}

// round 16
// speedup vs baseline: 1.5095x; 1.0764x over previous
#include <cuda_runtime.h>
#include <stdint.h>

// ============================================================================
// BinaryLinear: out = (mean|x| * mean|w|) * sign(x) @ sign(w)^T + bias
//   M=8192, N=4096, K=4096 (fp32 in/out)
// v14 (= v13 resubmit; container infra flake, kernel never reached nvcc):
// int8 +/-1 binarize, IMMA m16n8k32 s8 GEMM, ldmatrix.x4, BK=128, DEPTH=3
// cp.async ring, rolling A-fragment pipeline, fill spread across the 4 kt
// blocks (2 cp16/thread/kt) to avoid LSU bursts ahead of the LDSMs.
// ============================================================================

#define M_DIM 8192
#define N_DIM 4096
#define K_DIM 4096

#define BM 128
#define BN 128
#define BK 128                       // int8 K elements per pipeline chunk
#define NCHUNK (K_DIM / BK)          // 32
#define DEPTH 3

#define ASTRIDE 144                  // bytes per 128B row, padded (conflict-free)
#define A_SM_BYTES (BM * ASTRIDE)    // 18432
#define B_SM_BYTES (BN * ASTRIDE)    // 18432
#define STAGE_BYTES (A_SM_BYTES + B_SM_BYTES)   // 36864
#define SMEM_TOTAL (DEPTH * STAGE_BYTES)        // 110592

// ---- device scratch ----
__device__ int8_t g_Xb[(size_t)M_DIM * K_DIM];   // 32 MB
__device__ int8_t g_Wb[(size_t)N_DIM * K_DIM];   // 16 MB
__device__ float g_partX[2048];
__device__ float g_partW[1024];
__device__ float g_scale;

// ---- helpers ----
__device__ __forceinline__ uint32_t smem_u32(const void* p) {
    uint32_t a;
    asm("{ .reg .u64 t; cvta.to.shared.u64 t, %1; cvt.u32.u64 %0, t; }"
        : "=r"(a) : "l"(p));
    return a;
}

__device__ __forceinline__ void cp16(uint32_t saddr, const void* gaddr) {
    asm volatile("cp.async.cg.shared.global [%0], [%1], 16;\n"
                 :: "r"(saddr), "l"(gaddr));
}
__device__ __forceinline__ void cp_commit() {
    asm volatile("cp.async.commit_group;\n" ::);
}
template <int N>
__device__ __forceinline__ void cp_wait() {
    asm volatile("cp.async.wait_group %0;\n" :: "n"(N));
}

// ldmatrix x4: four 8x8 b16 tiles (8 rows x 16B each); lane l supplies the
// address of row (l&7) of tile (l>>3).
__device__ __forceinline__ void ldsm_x4(uint32_t* r, uint32_t addr) {
    asm volatile("ldmatrix.sync.aligned.m8n8.x4.shared.b16 {%0,%1,%2,%3}, [%4];"
                 : "=r"(r[0]), "=r"(r[1]), "=r"(r[2]), "=r"(r[3]) : "r"(addr));
}

// s8 x s8 -> s32 : D(16x8) += A(16x32) * B(32x8)
__device__ __forceinline__ void imma16832(int* c, const uint32_t* a,
                                          uint32_t b0, uint32_t b1) {
    asm volatile(
        "mma.sync.aligned.m16n8k32.row.col.s32.s8.s8.s32 "
        "{%0,%1,%2,%3}, {%4,%5,%6,%7}, {%8,%9}, {%0,%1,%2,%3};"
        : "+r"(c[0]), "+r"(c[1]), "+r"(c[2]), "+r"(c[3])
        : "r"(a[0]), "r"(a[1]), "r"(a[2]), "r"(a[3]),
          "r"(b0), "r"(b1));
}

// ============================================================================
// Phase 1: binarize fp32 -> int8 {-1,+1}, deterministic |.| partial sums
// ============================================================================
__device__ __forceinline__ void prep_body(const float4* __restrict__ in,
                                          uint32_t* __restrict__ out,
                                          int n4, float* __restrict__ partial) {
    float s = 0.f;
    const int stride = gridDim.x * blockDim.x;
    for (int i = blockIdx.x * blockDim.x + threadIdx.x; i < n4; i += stride) {
        float4 v = in[i];
        s += fabsf(v.x) + fabsf(v.y) + fabsf(v.z) + fabsf(v.w);
        uint32_t p = (v.x >= 0.f ? 0x01u : 0xFFu)
                   | ((v.y >= 0.f ? 0x01u : 0xFFu) << 8)
                   | ((v.z >= 0.f ? 0x01u : 0xFFu) << 16)
                   | ((v.w >= 0.f ? 0x01u : 0xFFu) << 24);
        out[i] = p;
    }
    __shared__ float sh[8];
    #pragma unroll
    for (int o = 16; o > 0; o >>= 1) s += __shfl_down_sync(0xFFFFFFFFu, s, o);
    if ((threadIdx.x & 31) == 0) sh[threadIdx.x >> 5] = s;
    __syncthreads();
    if (threadIdx.x == 0) {
        float t = 0.f;
        #pragma unroll
        for (int w = 0; w < 8; w++) t += sh[w];
        partial[blockIdx.x] = t;
    }
}

__global__ void prep_x_kernel(const float4* __restrict__ in) {
    prep_body(in, reinterpret_cast<uint32_t*>(g_Xb), (M_DIM * K_DIM) / 4, g_partX);
}
__global__ void prep_w_kernel(const float4* __restrict__ in) {
    prep_body(in, reinterpret_cast<uint32_t*>(g_Wb), (N_DIM * K_DIM) / 4, g_partW);
}

__global__ void finalize_kernel() {
    __shared__ float sh[256];
    int tid = threadIdx.x;
    float sx = 0.f;
    for (int i = tid; i < 2048; i += 256) sx += g_partX[i];
    sh[tid] = sx;
    __syncthreads();
    for (int o = 128; o > 0; o >>= 1) {
        if (tid < o) sh[tid] += sh[tid + o];
        __syncthreads();
    }
    float totx = sh[0];
    __syncthreads();
    float sw = 0.f;
    for (int i = tid; i < 1024; i += 256) sw += g_partW[i];
    sh[tid] = sw;
    __syncthreads();
    for (int o = 128; o > 0; o >>= 1) {
        if (tid < o) sh[tid] += sh[tid + o];
        __syncthreads();
    }
    if (tid == 0) {
        float ax = totx / ((float)M_DIM * (float)K_DIM);
        float aw = sh[0] / ((float)N_DIM * (float)K_DIM);
        g_scale = ax * aw;
    }
}

// ============================================================================
// Phase 2: IMMA GEMM, CTA 128x128, warp 64x32, 3-stage cp.async ring,
// BK=128 chunks, rolling-fragment ldmatrix pipeline, fill spread over kt.
// ============================================================================
// Quarter-fill: kt 0..1 load the A halves, kt 2..3 the B halves.
// 2 cp16 per thread per kt; 8 total per chunk.
__device__ __forceinline__ void fill_quarter(uint32_t stage_base,
                                             const int8_t* __restrict__ Ag,
                                             const int8_t* __restrict__ Bg,
                                             int tid, int kt) {
    if (kt < 2) {
        #pragma unroll
        for (int t = 0; t < 2; t++) {
            int idx = tid + (kt * 2 + t) * 256;
            int r = idx >> 3, g = idx & 7;
            cp16(stage_base + (uint32_t)(r * ASTRIDE + g * 16),
                 Ag + (size_t)r * K_DIM + g * 16);
        }
    } else {
        #pragma unroll
        for (int t = 0; t < 2; t++) {
            int idx = tid + ((kt - 2) * 2 + t) * 256;
            int r = idx >> 3, g = idx & 7;
            cp16(stage_base + A_SM_BYTES + (uint32_t)(r * ASTRIDE + g * 16),
                 Bg + (size_t)r * K_DIM + g * 16);
        }
    }
}

// Full-stage fill for the prologue.
__device__ __forceinline__ void fill_stage(uint32_t stage_base,
                                           const int8_t* __restrict__ Ag,
                                           const int8_t* __restrict__ Bg,
                                           int tid) {
    #pragma unroll
    for (int kt = 0; kt < 4; kt++)
        fill_quarter(stage_base, Ag, Bg, tid, kt);
}

__global__ void __launch_bounds__(256, 2)
gemm_kernel(const float* __restrict__ bias, float* __restrict__ out) {
    extern __shared__ char smem[];
    const uint32_t smem_base = smem_u32(smem);
    const int tid = threadIdx.x;
    const int wid = tid >> 5;
    const int lane = tid & 31;
    const int g = lane >> 2;          // mma group id (0..7)
    const int tig = lane & 3;         // thread in group

    const int warp_m = wid & 1;       // 2 x 64-row blocks
    const int warp_n = wid >> 1;      // 4 x 32-col blocks

    // raster: n-tiles fastest so concurrent CTAs share A row-blocks in L2
    const int n0 = (blockIdx.x & 31) * BN;
    const int m0 = (blockIdx.x >> 5) * BM;

    const int8_t* Abase = g_Xb + (size_t)m0 * K_DIM;
    const int8_t* Bbase = g_Wb + (size_t)n0 * K_DIM;

    int acc[4][4][4];
    #pragma unroll
    for (int i = 0; i < 4; i++)
        #pragma unroll
        for (int j = 0; j < 4; j++)
            #pragma unroll
            for (int q = 0; q < 4; q++) acc[i][j][q] = 0;

    // prologue: fill chunks 0..DEPTH-2
    #pragma unroll
    for (int p = 0; p < DEPTH - 1; p++) {
        fill_stage(smem_base + p * STAGE_BYTES,
                   Abase + (size_t)p * BK, Bbase + (size_t)p * BK, tid);
        cp_commit();
    }

    // ---- ldmatrix per-lane base offsets (within a stage) ----
    const int a_row = warp_m * 64 + (lane & 7) + ((lane >> 3) & 1) * 8;
    const uint32_t a_off = (uint32_t)(a_row * ASTRIDE + (lane >> 4) * 16);
    const int b_row = warp_n * 32 + ((lane >> 4) * 8) + (lane & 7);
    const uint32_t b_off = (uint32_t)(A_SM_BYTES + b_row * ASTRIDE
                                      + (((lane >> 3) & 1) * 16));

    for (int c = 0; c < NCHUNK; c++) {
        cp_wait<DEPTH - 2>();     // chunk c resident (uniform commit count)
        __syncthreads();          // all threads done with stage (c-1)%DEPTH

        const int fc = c + DEPTH - 1;       // chunk to fill this iteration
        const bool do_fill = (fc < NCHUNK);
        const uint32_t fill_base = smem_base + (uint32_t)((fc % DEPTH) * STAGE_BYTES);
        const int8_t* fa = Abase + (size_t)fc * BK;
        const int8_t* fb = Bbase + (size_t)fc * BK;
        const uint32_t SA = smem_base + (uint32_t)((c % DEPTH) * STAGE_BYTES);

        #pragma unroll
        for (int kt = 0; kt < 4; kt++) {    // 4 x 32B K-steps per chunk
            uint32_t b[2][4];
            uint32_t a[2][4];               // rolling A fragments
            #pragma unroll
            for (int p = 0; p < 2; p++)
                ldsm_x4(b[p], SA + b_off + (uint32_t)(p * 16 * ASTRIDE + kt * 32));
            ldsm_x4(a[0], SA + a_off + (uint32_t)(kt * 32));
            #pragma unroll
            for (int mt = 0; mt < 4; mt++) {
                if (mt < 3)
                    ldsm_x4(a[(mt + 1) & 1],
                            SA + a_off + (uint32_t)((mt + 1) * 16 * ASTRIDE + kt * 32));
                #pragma unroll
                for (int nt = 0; nt < 4; nt++)
                    imma16832(acc[mt][nt], a[mt & 1],
                              b[nt >> 1][(nt & 1) * 2], b[nt >> 1][(nt & 1) * 2 + 1]);
            }
            // spread fill: 2 cp16/thread after each kt's compute block
            if (do_fill)
                fill_quarter(fill_base, fa, fb, tid, kt);
            if (kt == 3)
                cp_commit();      // one commit per iteration -> uniform count
        }
    }

    // epilogue: scale + bias, float2 stores
    const float scale = g_scale;
    #pragma unroll
    for (int mt = 0; mt < 4; mt++) {
        const int r0 = m0 + warp_m * 64 + mt * 16 + g;
        const int r1 = r0 + 8;
        #pragma unroll
        for (int nt = 0; nt < 4; nt++) {
            const int col = n0 + warp_n * 32 + nt * 8 + tig * 2;
            const float2 bv = *reinterpret_cast<const float2*>(bias + col);
            float2 o0, o1;
            o0.x = (float)acc[mt][nt][0] * scale + bv.x;
            o0.y = (float)acc[mt][nt][1] * scale + bv.y;
            o1.x = (float)acc[mt][nt][2] * scale + bv.x;
            o1.y = (float)acc[mt][nt][3] * scale + bv.y;
            *reinterpret_cast<float2*>(out + (size_t)r0 * N_DIM + col) = o0;
            *reinterpret_cast<float2*>(out + (size_t)r1 * N_DIM + col) = o1;
        }
    }
}

// ============================================================================
// launch
// ============================================================================
extern "C" void kernel_launch(void* const* d_in, const int* in_sizes, int n_in,
                              void* d_out, int out_size) {
    const float* x    = (const float*)d_in[0];
    const float* w    = (const float*)d_in[1];
    const float* bias = (const float*)d_in[2];
    float* out = (float*)d_out;

    cudaFuncSetAttribute(gemm_kernel, cudaFuncAttributeMaxDynamicSharedMemorySize,
                         SMEM_TOTAL);

    prep_x_kernel<<<2048, 256>>>((const float4*)x);
    prep_w_kernel<<<1024, 256>>>((const float4*)w);
    finalize_kernel<<<1, 256>>>();
    gemm_kernel<<<(M_DIM / BM) * (N_DIM / BN), 256, SMEM_TOTAL>>>(bias, out);
}